// round 13
// baseline (speedup 1.0000x reference)
#include <cuda_runtime.h>
#include <cuda_bf16.h>
#include <stdint.h>

#define RBOX   500000
#define KCLS   10
#define NSCAL  (RBOX * 11)
#define NV4    (NSCAL / 4)
#define TTOP   2048
#define SCORE_T 0.05f
#define NMS_T   0.5f
#define CLS_OFF 3001.0f
#define IMG_W   1920.0f
#define IMG_H   1080.0f

#define HBASE  125542u              // bits(0.05f) >> 13
#define HBINS  4506
#define CAP    6144

#define RMT    512                  // k_rowmax threads
#define RMC    4                    // chunks per block
#define RMROWS 512                  // rows per chunk
#define RMB    245                  // 245 * 2048 rows >= RBOX
#define NGRP   (RBOX / 32)          // 15625 row-groups (exact)

#define MLIST  512                  // per-class list capacity (~205 expected)
#define NW     (MLIST / 32)         // 16 mask words

// ---------------- device scratch ----------------
__device__ unsigned int       g_hist[HBINS];
__device__ unsigned int       g_rowmax[RBOX];
__device__ unsigned int       g_grpmax[NGRP];
__device__ unsigned int       g_done;
__device__ unsigned int       g_cutbin;
__device__ unsigned int       g_cnt;
__device__ unsigned long long g_keys[CAP];
__device__ float              g_nbox[TTOP * 4];   // class-offset boxes (exact ref arithmetic)
__device__ float              g_obox[TTOP * 4];   // clipped boxes for output
__device__ float              g_oscore[TTOP];
__device__ unsigned char      g_cls[TTOP];

// ======== kernel 1: row max + histogram + group max + fused scan (last block) ========
__global__ void __launch_bounds__(RMT) k_rowmax(const float* __restrict__ scores,
                                                const float* __restrict__ center) {
    __shared__ __align__(16) float4 srow4[RMROWS * 11 / 4];   // 22528 B
    __shared__ unsigned sh[HBINS];                            // 18024 B
    __shared__ unsigned s_last;
    __shared__ unsigned wsum[16];
    __shared__ unsigned wsuf[17];
    float* srow = (float*)srow4;
    int t = threadIdx.x;
    unsigned lane = (unsigned)t & 31u, wid = (unsigned)t >> 5;
    for (int i = t; i < HBINS; i += RMT) sh[i] = 0u;

    unsigned blockrow0 = blockIdx.x * (RMROWS * RMC);
    for (int ch = 0; ch < RMC; ch++) {
        unsigned row0 = blockrow0 + (unsigned)ch * RMROWS;
        __syncthreads();                       // srow reuse + first-iter hist-zero cover
        if (row0 < RBOX) {
            unsigned base = (row0 * 11u) / 4u; // row0 multiple of 512 -> exact
            #pragma unroll
            for (int i = 0; i < 3; i++) {      // 3*512 = 1536 >= 1408
                unsigned li = (unsigned)i * RMT + (unsigned)t;
                if (li < RMROWS * 11 / 4) {
                    unsigned gq = base + li;
                    float4 v = (gq < NV4) ? __ldg(&((const float4*)scores)[gq])
                                          : make_float4(0.f, 0.f, 0.f, 0.f);
                    srow4[li] = v;
                }
            }
        }
        __syncthreads();
        unsigned r = row0 + (unsigned)t;
        unsigned bits = 0u;
        if (r < RBOX) {
            float c = __ldg(&center[r]);
            const float* rp = srow + t * 11 + 1;
            float m = rp[0];
            #pragma unroll
            for (int k = 1; k < 10; k++) m = fmaxf(m, rp[k]);
            float fg = m * c;
            if (fg > SCORE_T) {
                bits = __float_as_uint(fg);
                unsigned bin = (bits >> 13) - HBASE;
                if (bin >= HBINS) bin = HBINS - 1;
                atomicAdd(&sh[bin], 1u);
            }
            g_rowmax[r] = bits;
        }
        unsigned gmax = bits;                  // 32-row group max
        #pragma unroll
        for (int off = 16; off > 0; off >>= 1)
            gmax = max(gmax, __shfl_xor_sync(0xFFFFFFFFu, gmax, off));
        unsigned grp0 = row0 + (wid << 5);
        if (lane == 0u && grp0 < RBOX) g_grpmax[grp0 >> 5] = gmax;
    }
    __syncthreads();
    for (int i = t; i < HBINS; i += RMT) {
        unsigned v = sh[i];
        if (v) atomicAdd(&g_hist[i], v);
    }
    // -------- last-block-done -> suffix scan for theta_r --------
    __threadfence();
    __syncthreads();
    if (t == 0) s_last = (atomicAdd(&g_done, 1u) == RMB - 1u) ? 1u : 0u;
    __syncthreads();
    if (!s_last) return;

    const int CH = 9;                          // 512*9 = 4608 >= HBINS
    int lo = t * CH;
    unsigned loc[CH];
    unsigned p = 0u;
    #pragma unroll
    for (int k = 0; k < CH; k++) {
        int bin = lo + k;
        unsigned v = (bin < HBINS) ? __ldcg(&g_hist[bin]) : 0u;
        loc[k] = v; p += v;
    }
    unsigned s = p;                            // warp suffix scan
    #pragma unroll
    for (int off = 1; off < 32; off <<= 1) {
        unsigned v = __shfl_down_sync(0xFFFFFFFFu, s, off);
        if (lane + off < 32) s += v;
    }
    if (lane == 0u) wsum[wid] = s;
    __syncthreads();
    if (wid == 0u) {
        unsigned ws = (lane < 16u) ? wsum[lane] : 0u;
        #pragma unroll
        for (int off = 1; off < 32; off <<= 1) {
            unsigned v = __shfl_down_sync(0xFFFFFFFFu, ws, off);
            if (lane + off < 32) ws += v;
        }
        if (lane < 16u) wsuf[lane] = ws;
    }
    __syncthreads();
    unsigned sincl = s + ((wid < 15u) ? wsuf[wid + 1] : 0u);
    unsigned total = wsuf[0];
    if (total >= TTOP) {
        unsigned above = sincl - p;
        if (above < TTOP && sincl >= TTOP) {   // unique crossing thread
            unsigned run = above;
            for (int k = CH - 1; k >= 0; k--) {
                run += loc[k];
                if (run >= TTOP) { g_cutbin = (unsigned)(lo + k); break; }
            }
        }
    } else if (t == 0) {
        g_cutbin = 0u;
    }
    for (int bin = t; bin < HBINS; bin += RMT) g_hist[bin] = 0u;
    if (t == 0) { g_cnt = 0u; g_done = 0u; }
}

// ======== kernel 2: collect candidate keys (warp per 32-row group, skip) ========
__global__ void __launch_bounds__(256) k_collect(const float* __restrict__ scores,
                                                 const float* __restrict__ center) {
    unsigned grp = (blockIdx.x * 256u + threadIdx.x) >> 5;
    unsigned lane = threadIdx.x & 31u;
    if (grp >= NGRP) return;
    unsigned cutb = HBASE + g_cutbin;                 // theta_r bin
    unsigned gmax = __ldg(&g_grpmax[grp]);
    if ((gmax >> 13) < cutb) return;                  // most groups skip here
    unsigned r = grp * 32u + lane;                    // r < RBOX (NGRP*32 == RBOX)
    unsigned bits = __ldg(&g_rowmax[r]);
    if ((bits >> 13) < cutb) return;
    float c = __ldg(&center[r]);
    const float* rp = scores + r * 11u + 1u;
    #pragma unroll
    for (int k = 0; k < 10; k++) {
        float fg = __ldg(&rp[k]) * c;
        if (fg > SCORE_T) {
            unsigned cb = __float_as_uint(fg);
            if ((cb >> 13) >= cutb) {
                unsigned j = r * 10u + (unsigned)k;
                unsigned pos = atomicAdd(&g_cnt, 1u);
                if (pos < CAP) {
                    g_keys[pos] = ((unsigned long long)cb << 32) |
                                  (unsigned long long)(0xFFFFFFFFu - j);
                }
            }
        }
    }
}

// ======== kernel 3: rank-by-count (L1-resident keys, warp per candidate) ========
__global__ void __launch_bounds__(1024) k_rank(const float* __restrict__ boxes) {
    unsigned n = g_cnt; if (n > CAP) n = CAP;
    unsigned cand = (blockIdx.x * 1024u + threadIdx.x) >> 5;
    unsigned lane = threadIdx.x & 31u;
    if (cand >= n) return;
    unsigned long long mykey = __ldg(&g_keys[cand]);
    unsigned cnt = 0u;
    for (unsigned j = lane; j < n; j += 32u)
        cnt += (__ldg(&g_keys[j]) > mykey) ? 1u : 0u;
    #pragma unroll
    for (int off = 16; off > 0; off >>= 1)
        cnt += __shfl_xor_sync(0xFFFFFFFFu, cnt, off);
    if (lane == 0u && cnt < TTOP) {
        unsigned rank = cnt;
        unsigned j = 0xFFFFFFFFu - (unsigned)(mykey & 0xFFFFFFFFull);
        float s = __uint_as_float((unsigned)(mykey >> 32));
        unsigned r = j / 10u;
        unsigned cls = j - r * 10u;
        float x1 = boxes[r * 4 + 0], y1 = boxes[r * 4 + 1];
        float x2 = boxes[r * 4 + 2], y2 = boxes[r * 4 + 3];
        float b0 = fminf(fmaxf(x1, 0.f), IMG_W);
        float b1 = fminf(fmaxf(y1, 0.f), IMG_H);
        float b2 = fminf(fmaxf(x2, 0.f), IMG_W);
        float b3 = fminf(fmaxf(y2, 0.f), IMG_H);
        float off2 = (float)cls * CLS_OFF;
        g_obox[rank * 4 + 0] = b0; g_obox[rank * 4 + 1] = b1;
        g_obox[rank * 4 + 2] = b2; g_obox[rank * 4 + 3] = b3;
        g_nbox[rank * 4 + 0] = b0 + off2; g_nbox[rank * 4 + 1] = b1 + off2;
        g_nbox[rank * 4 + 2] = b2 + off2; g_nbox[rank * 4 + 3] = b3 + off2;
        g_oscore[rank] = s;
        g_cls[rank] = (unsigned char)cls;
    }
}

// ======== kernel 4: per-class exact greedy NMS (bitmask) + direct output ========
// Cross-class suppression impossible (offset 3001 > image extent) -> global
// greedy NMS == independent per-class greedy NMS. 10 blocks, one class each.
// IoU computed on the OFFSET boxes with the exact reference formula ->
// bit-identical decisions to the reference fori_loop.
__global__ void __launch_bounds__(1024) k_nms(float* __restrict__ out) {
    __shared__ float sx1[MLIST], sy1[MLIST], sx2[MLIST], sy2[MLIST];  // 8 KB
    __shared__ unsigned short sidx[MLIST];                            // 1 KB
    __shared__ unsigned srow[MLIST * NW];                             // 32 KB
    __shared__ unsigned char skeep[MLIST];
    __shared__ unsigned s_woff[32];
    __shared__ unsigned s_tot;
    int t = threadIdx.x;
    int c = blockIdx.x;
    unsigned lane = (unsigned)t & 31u, wid = (unsigned)t >> 5;

    unsigned nvalid = g_cnt; if (nvalid > TTOP) nvalid = TTOP;

    // zero suppression rows
    for (int k = t; k < MLIST * NW; k += 1024) srow[k] = 0u;

    // ---- rank-ORDERED compaction of this class's entries (ballot prefix scan) ----
    unsigned base = 0u;
    #pragma unroll
    for (int chunk = 0; chunk < 2; chunk++) {
        int i = chunk * 1024 + t;
        bool match = (i < (int)nvalid) && ((int)g_cls[i] == c);
        unsigned bal = __ballot_sync(0xFFFFFFFFu, match);
        unsigned pre = __popc(bal & ((1u << lane) - 1u));
        if (lane == 0u) s_woff[wid] = __popc(bal);
        __syncthreads();
        if (wid == 0u) {
            unsigned v = s_woff[lane];
            unsigned sc = v;
            #pragma unroll
            for (int o = 1; o < 32; o <<= 1) {
                unsigned u = __shfl_up_sync(0xFFFFFFFFu, sc, o);
                if (lane >= (unsigned)o) sc += u;
            }
            s_woff[lane] = sc - v;              // exclusive
            if (lane == 31u) s_tot = sc;        // inclusive total
        }
        __syncthreads();
        unsigned pos = base + s_woff[wid] + pre;
        if (match && pos < MLIST) {
            sidx[pos] = (unsigned short)i;
            sx1[pos] = g_nbox[i * 4 + 0];
            sy1[pos] = g_nbox[i * 4 + 1];
            sx2[pos] = g_nbox[i * 4 + 2];
            sy2[pos] = g_nbox[i * 4 + 3];
        }
        base += s_tot;
        __syncthreads();
    }
    unsigned m = base; if (m > MLIST) m = MLIST;

    // ---- suppression rows: warp per p, ballot over q-words ----
    unsigned nwm = (m + 31u) >> 5;
    for (unsigned p = wid; p < m; p += 32u) {
        float ax1 = sx1[p], ay1 = sy1[p], ax2 = sx2[p], ay2 = sy2[p];
        float aarea = fmaxf(ax2 - ax1, 0.f) * fmaxf(ay2 - ay1, 0.f);
        for (unsigned wk = p >> 5; wk < nwm; wk++) {
            unsigned q = wk * 32u + lane;
            bool sup = false;
            if (q > p && q < m) {
                float w = fminf(ax2, sx2[q]) - fmaxf(ax1, sx1[q]);
                float h = fminf(ay2, sy2[q]) - fmaxf(ay1, sy1[q]);
                if (w > 0.f && h > 0.f) {
                    float inter = w * h;
                    float barea = fmaxf(sx2[q] - sx1[q], 0.f) * fmaxf(sy2[q] - sy1[q], 0.f);
                    float denom = aarea + barea - inter + 1e-9f;
                    if (inter > 0.45f * denom) {
                        sup = (inter / denom) > NMS_T;   // exact IEEE div (rare)
                    }
                }
            }
            unsigned word = __ballot_sync(0xFFFFFFFFu, sup);
            if (lane == 0u) srow[p * NW + wk] = word;
        }
    }
    __syncthreads();

    // ---- serial greedy scan (warp 0; lane l owns removed word l) ----
    if (wid == 0u) {
        unsigned removed = 0u;
        for (unsigned w = 0; w < nwm; w++) {
            unsigned rw = __shfl_sync(0xFFFFFFFFu, removed, (int)w);
            unsigned iend = min(m, (w + 1u) * 32u);
            for (unsigned i = w * 32u; i < iend; i++) {
                bool kp = ((rw >> (i & 31u)) & 1u) == 0u;
                unsigned rowl = (lane < NW) ? srow[i * NW + lane] : 0u;
                unsigned roww = srow[i * NW + w];
                if (kp) { removed |= rowl; rw |= roww; }
                if (lane == 0u) skeep[i] = kp ? 1 : 0;
            }
        }
    }
    __syncthreads();

    // ---- output: each class block writes its own ranks ----
    for (unsigned p = t; p < m; p += 1024u) {
        unsigned i = sidx[p];
        bool kp = skeep[p] != 0;
        out[i * 5 + 0] = kp ? g_obox[i * 4 + 0] : 0.f;
        out[i * 5 + 1] = kp ? g_obox[i * 4 + 1] : 0.f;
        out[i * 5 + 2] = kp ? g_obox[i * 4 + 2] : 0.f;
        out[i * 5 + 3] = kp ? g_obox[i * 4 + 3] : 0.f;
        out[i * 5 + 4] = kp ? g_oscore[i] : 0.f;
    }
    // safety: zero any slots beyond nvalid (normally none; n >= 2048)
    if (c == 0) {
        for (unsigned i = nvalid + t; i < TTOP; i += 1024u) {
            out[i * 5 + 0] = 0.f; out[i * 5 + 1] = 0.f; out[i * 5 + 2] = 0.f;
            out[i * 5 + 3] = 0.f; out[i * 5 + 4] = 0.f;
        }
    }
}

// ---------------- launch ----------------
extern "C" void kernel_launch(void* const* d_in, const int* in_sizes, int n_in,
                              void* d_out, int out_size) {
    const float* boxes  = nullptr;
    const float* scores = nullptr;
    const float* center = nullptr;
    for (int i = 0; i < n_in; i++) {
        if (in_sizes[i] == RBOX * 4)       boxes  = (const float*)d_in[i];
        else if (in_sizes[i] == RBOX * 11) scores = (const float*)d_in[i];
        else if (in_sizes[i] == RBOX)      center = (const float*)d_in[i];
    }
    if (!boxes)  boxes  = (const float*)d_in[0];
    if (!scores) scores = (const float*)d_in[1];
    if (!center) center = (const float*)d_in[2];
    float* out = (float*)d_out;

    k_rowmax<<<RMB, RMT>>>(scores, center);                    // + fused theta_r scan
    k_collect<<<(NGRP * 32 + 255) / 256, 256>>>(scores, center);
    k_rank<<<(CAP * 32 + 1023) / 1024, 1024>>>(boxes);
    k_nms<<<KCLS, 1024>>>(out);                                // per-class greedy + output
}

// round 14
// speedup vs baseline: 1.0584x; 1.0584x over previous
#include <cuda_runtime.h>
#include <cuda_bf16.h>
#include <stdint.h>

#define RBOX   500000
#define KCLS   10
#define NSCAL  (RBOX * 11)
#define NV4    (NSCAL / 4)
#define TTOP   2048
#define SCORE_T 0.05f
#define NMS_T   0.5f
#define CLS_OFF 3001.0f
#define IMG_W   1920.0f
#define IMG_H   1080.0f

#define HBASE  125542u              // bits(0.05f) >> 13
#define HBINS  4506
#define CAP    6144

#define RMT    512                  // k_rowmax threads
#define RMC    4                    // chunks per block
#define RMROWS 512                  // rows per chunk
#define RMB    245                  // 245 * 2048 rows >= RBOX
#define NGRP   (RBOX / 32)          // 15625 row-groups (exact)

#define MLIST  512                  // per-class list capacity (~205 expected)
#define NW     (MLIST / 32)         // 16 mask words

// ---------------- device scratch ----------------
__device__ unsigned int       g_hist[HBINS];
__device__ unsigned int       g_rowmax[RBOX];
__device__ unsigned int       g_grpmax[NGRP];
__device__ unsigned int       g_done;
__device__ unsigned int       g_cutbin;
__device__ unsigned int       g_cnt;
__device__ unsigned long long g_keys[CAP];
__device__ float              g_nbox[TTOP * 4];   // class-offset boxes (exact ref arithmetic)
__device__ float              g_obox[TTOP * 4];   // clipped boxes for output
__device__ float              g_oscore[TTOP];
__device__ unsigned char      g_cls[TTOP];

// ======== kernel 1: row max + histogram + group max + fused scan (last block) ========
__global__ void __launch_bounds__(RMT) k_rowmax(const float* __restrict__ scores,
                                                const float* __restrict__ center) {
    __shared__ __align__(16) float4 srow4[RMROWS * 11 / 4];   // 22528 B
    __shared__ unsigned sh[HBINS];                            // 18024 B
    __shared__ unsigned s_last;
    __shared__ unsigned wsum[16];
    __shared__ unsigned wsuf[17];
    float* srow = (float*)srow4;
    int t = threadIdx.x;
    unsigned lane = (unsigned)t & 31u, wid = (unsigned)t >> 5;
    for (int i = t; i < HBINS; i += RMT) sh[i] = 0u;

    unsigned blockrow0 = blockIdx.x * (RMROWS * RMC);
    for (int ch = 0; ch < RMC; ch++) {
        unsigned row0 = blockrow0 + (unsigned)ch * RMROWS;
        __syncthreads();                       // srow reuse + first-iter hist-zero cover
        if (row0 < RBOX) {
            unsigned base = (row0 * 11u) / 4u; // row0 multiple of 512 -> exact
            #pragma unroll
            for (int i = 0; i < 3; i++) {      // 3*512 = 1536 >= 1408
                unsigned li = (unsigned)i * RMT + (unsigned)t;
                if (li < RMROWS * 11 / 4) {
                    unsigned gq = base + li;
                    float4 v = (gq < NV4) ? __ldg(&((const float4*)scores)[gq])
                                          : make_float4(0.f, 0.f, 0.f, 0.f);
                    srow4[li] = v;
                }
            }
        }
        __syncthreads();
        unsigned r = row0 + (unsigned)t;
        unsigned bits = 0u;
        if (r < RBOX) {
            float c = __ldg(&center[r]);
            const float* rp = srow + t * 11 + 1;
            float m = rp[0];
            #pragma unroll
            for (int k = 1; k < 10; k++) m = fmaxf(m, rp[k]);
            float fg = m * c;
            if (fg > SCORE_T) {
                bits = __float_as_uint(fg);
                unsigned bin = (bits >> 13) - HBASE;
                if (bin >= HBINS) bin = HBINS - 1;
                atomicAdd(&sh[bin], 1u);
            }
            g_rowmax[r] = bits;
        }
        unsigned gmax = bits;                  // 32-row group max
        #pragma unroll
        for (int off = 16; off > 0; off >>= 1)
            gmax = max(gmax, __shfl_xor_sync(0xFFFFFFFFu, gmax, off));
        unsigned grp0 = row0 + (wid << 5);
        if (lane == 0u && grp0 < RBOX) g_grpmax[grp0 >> 5] = gmax;
    }
    __syncthreads();
    for (int i = t; i < HBINS; i += RMT) {
        unsigned v = sh[i];
        if (v) atomicAdd(&g_hist[i], v);
    }
    // -------- last-block-done -> suffix scan for theta_r --------
    __threadfence();
    __syncthreads();
    if (t == 0) s_last = (atomicAdd(&g_done, 1u) == RMB - 1u) ? 1u : 0u;
    __syncthreads();
    if (!s_last) return;

    const int CH = 9;                          // 512*9 = 4608 >= HBINS
    int lo = t * CH;
    unsigned loc[CH];
    unsigned p = 0u;
    #pragma unroll
    for (int k = 0; k < CH; k++) {
        int bin = lo + k;
        unsigned v = (bin < HBINS) ? __ldcg(&g_hist[bin]) : 0u;
        loc[k] = v; p += v;
    }
    unsigned s = p;                            // warp suffix scan
    #pragma unroll
    for (int off = 1; off < 32; off <<= 1) {
        unsigned v = __shfl_down_sync(0xFFFFFFFFu, s, off);
        if (lane + off < 32) s += v;
    }
    if (lane == 0u) wsum[wid] = s;
    __syncthreads();
    if (wid == 0u) {
        unsigned ws = (lane < 16u) ? wsum[lane] : 0u;
        #pragma unroll
        for (int off = 1; off < 32; off <<= 1) {
            unsigned v = __shfl_down_sync(0xFFFFFFFFu, ws, off);
            if (lane + off < 32) ws += v;
        }
        if (lane < 16u) wsuf[lane] = ws;
    }
    __syncthreads();
    unsigned sincl = s + ((wid < 15u) ? wsuf[wid + 1] : 0u);
    unsigned total = wsuf[0];
    if (total >= TTOP) {
        unsigned above = sincl - p;
        if (above < TTOP && sincl >= TTOP) {   // unique crossing thread
            unsigned run = above;
            for (int k = CH - 1; k >= 0; k--) {
                run += loc[k];
                if (run >= TTOP) { g_cutbin = (unsigned)(lo + k); break; }
            }
        }
    } else if (t == 0) {
        g_cutbin = 0u;
    }
    for (int bin = t; bin < HBINS; bin += RMT) g_hist[bin] = 0u;
    if (t == 0) { g_cnt = 0u; g_done = 0u; }
}

// ======== kernel 2: collect candidate keys (warp per 32-row group, skip) ========
__global__ void __launch_bounds__(256) k_collect(const float* __restrict__ scores,
                                                 const float* __restrict__ center) {
    unsigned grp = (blockIdx.x * 256u + threadIdx.x) >> 5;
    unsigned lane = threadIdx.x & 31u;
    if (grp >= NGRP) return;
    unsigned cutb = HBASE + g_cutbin;                 // theta_r bin
    unsigned gmax = __ldg(&g_grpmax[grp]);
    if ((gmax >> 13) < cutb) return;                  // most groups skip here
    unsigned r = grp * 32u + lane;                    // r < RBOX (NGRP*32 == RBOX)
    unsigned bits = __ldg(&g_rowmax[r]);
    if ((bits >> 13) < cutb) return;
    float c = __ldg(&center[r]);
    const float* rp = scores + r * 11u + 1u;
    #pragma unroll
    for (int k = 0; k < 10; k++) {
        float fg = __ldg(&rp[k]) * c;
        if (fg > SCORE_T) {
            unsigned cb = __float_as_uint(fg);
            if ((cb >> 13) >= cutb) {
                unsigned j = r * 10u + (unsigned)k;
                unsigned pos = atomicAdd(&g_cnt, 1u);
                if (pos < CAP) {
                    g_keys[pos] = ((unsigned long long)cb << 32) |
                                  (unsigned long long)(0xFFFFFFFFu - j);
                }
            }
        }
    }
}

// ======== kernel 3: rank-by-count (L1-resident keys, warp per candidate) ========
__global__ void __launch_bounds__(1024) k_rank(const float* __restrict__ boxes) {
    unsigned n = g_cnt; if (n > CAP) n = CAP;
    unsigned cand = (blockIdx.x * 1024u + threadIdx.x) >> 5;
    unsigned lane = threadIdx.x & 31u;
    if (cand >= n) return;
    unsigned long long mykey = __ldg(&g_keys[cand]);
    unsigned cnt = 0u;
    for (unsigned j = lane; j < n; j += 32u)
        cnt += (__ldg(&g_keys[j]) > mykey) ? 1u : 0u;
    #pragma unroll
    for (int off = 16; off > 0; off >>= 1)
        cnt += __shfl_xor_sync(0xFFFFFFFFu, cnt, off);
    if (lane == 0u && cnt < TTOP) {
        unsigned rank = cnt;
        unsigned j = 0xFFFFFFFFu - (unsigned)(mykey & 0xFFFFFFFFull);
        float s = __uint_as_float((unsigned)(mykey >> 32));
        unsigned r = j / 10u;
        unsigned cls = j - r * 10u;
        float x1 = boxes[r * 4 + 0], y1 = boxes[r * 4 + 1];
        float x2 = boxes[r * 4 + 2], y2 = boxes[r * 4 + 3];
        float b0 = fminf(fmaxf(x1, 0.f), IMG_W);
        float b1 = fminf(fmaxf(y1, 0.f), IMG_H);
        float b2 = fminf(fmaxf(x2, 0.f), IMG_W);
        float b3 = fminf(fmaxf(y2, 0.f), IMG_H);
        float off2 = (float)cls * CLS_OFF;
        g_obox[rank * 4 + 0] = b0; g_obox[rank * 4 + 1] = b1;
        g_obox[rank * 4 + 2] = b2; g_obox[rank * 4 + 3] = b3;
        g_nbox[rank * 4 + 0] = b0 + off2; g_nbox[rank * 4 + 1] = b1 + off2;
        g_nbox[rank * 4 + 2] = b2 + off2; g_nbox[rank * 4 + 3] = b3 + off2;
        g_oscore[rank] = s;
        g_cls[rank] = (unsigned char)cls;
    }
}

// ======== kernel 4: per-class exact greedy NMS (transposed sparse masks) ========
// Cross-class suppression impossible (offset 3001 > image extent) -> global
// greedy == per-class greedy. Warp per suppressee q builds its suppressor
// mask (exact reference IoU on offset boxes). Resolution touches ONLY boxes
// with non-empty masks (rare), so the sequential tail is ~#edges, not m.
__global__ void __launch_bounds__(1024) k_nms(float* __restrict__ out) {
    __shared__ float sx1[MLIST], sy1[MLIST], sx2[MLIST], sy2[MLIST];  // 8 KB
    __shared__ unsigned short sidx[MLIST];                            // 1 KB
    __shared__ unsigned smask[MLIST * NW];                            // 32 KB
    __shared__ unsigned char sintr[MLIST];
    __shared__ unsigned skw[NW];
    __shared__ unsigned s_woff[32];
    __shared__ unsigned s_tot;
    int t = threadIdx.x;
    int c = blockIdx.x;
    unsigned lane = (unsigned)t & 31u, wid = (unsigned)t >> 5;

    unsigned nvalid = g_cnt; if (nvalid > TTOP) nvalid = TTOP;

    // ---- rank-ORDERED compaction of this class's entries (ballot prefix scan) ----
    unsigned base = 0u;
    #pragma unroll
    for (int chunk = 0; chunk < 2; chunk++) {
        int i = chunk * 1024 + t;
        bool match = (i < (int)nvalid) && ((int)g_cls[i] == c);
        unsigned bal = __ballot_sync(0xFFFFFFFFu, match);
        unsigned pre = __popc(bal & ((1u << lane) - 1u));
        if (lane == 0u) s_woff[wid] = __popc(bal);
        __syncthreads();
        if (wid == 0u) {
            unsigned v = s_woff[lane];
            unsigned sc = v;
            #pragma unroll
            for (int o = 1; o < 32; o <<= 1) {
                unsigned u = __shfl_up_sync(0xFFFFFFFFu, sc, o);
                if (lane >= (unsigned)o) sc += u;
            }
            s_woff[lane] = sc - v;              // exclusive
            if (lane == 31u) s_tot = sc;        // inclusive total
        }
        __syncthreads();
        unsigned pos = base + s_woff[wid] + pre;
        if (match && pos < MLIST) {
            sidx[pos] = (unsigned short)i;
            sx1[pos] = g_nbox[i * 4 + 0];
            sy1[pos] = g_nbox[i * 4 + 1];
            sx2[pos] = g_nbox[i * 4 + 2];
            sy2[pos] = g_nbox[i * 4 + 3];
        }
        base += s_tot;
        __syncthreads();
    }
    unsigned m = base; if (m > MLIST) m = MLIST;
    unsigned nwm = (m + 31u) >> 5;

    // ---- suppressor masks: warp per q, lanes per p (ballot per 32-p word) ----
    for (unsigned q = wid; q < m; q += 32u) {
        float qx1 = sx1[q], qy1 = sy1[q], qx2 = sx2[q], qy2 = sy2[q];
        float qarea = fmaxf(qx2 - qx1, 0.f) * fmaxf(qy2 - qy1, 0.f);
        unsigned acc = 0u;
        for (unsigned wk = 0; wk < nwm; wk++) {
            unsigned p = wk * 32u + lane;
            bool sup = false;
            if (p < q) {
                float px1 = sx1[p], py1 = sy1[p], px2 = sx2[p], py2 = sy2[p];
                float w = fminf(px2, qx2) - fmaxf(px1, qx1);
                float h = fminf(py2, qy2) - fmaxf(py1, qy1);
                if (w > 0.f && h > 0.f) {
                    float inter = w * h;
                    float parea = fmaxf(px2 - px1, 0.f) * fmaxf(py2 - py1, 0.f);
                    float denom = parea + qarea - inter + 1e-9f;   // ref order: area_i+area_j
                    if (inter > 0.45f * denom)
                        sup = (inter / denom) > NMS_T;             // exact IEEE div (rare)
                }
            }
            unsigned word = __ballot_sync(0xFFFFFFFFu, sup);
            if (lane == 0u) smask[q * NW + wk] = word;
            acc |= word;
        }
        if (lane == 0u) sintr[q] = (acc != 0u) ? 1 : 0;
    }
    __syncthreads();

    // ---- sparse greedy resolution (warp 0; lane l holds keep word l) ----
    if (wid == 0u) {
        unsigned kw = 0u;                       // keep word for lane's 32 q's
        if (lane < nwm) {
            kw = 0xFFFFFFFFu;
            if (lane == nwm - 1u && (m & 31u)) kw = (1u << (m & 31u)) - 1u;
        }
        for (unsigned w = 0; w < nwm; w++) {
            unsigned qq = w * 32u + lane;
            unsigned intr = __ballot_sync(0xFFFFFFFFu, (qq < m) && sintr[qq]);
            while (intr) {
                int b = __ffs(intr) - 1; intr &= intr - 1u;
                unsigned q = w * 32u + (unsigned)b;
                unsigned mw = (lane < nwm) ? smask[q * NW + lane] : 0u;
                // suppressors are strictly < q: bits >= b of word w are zero in mw,
                // bits < b of kw[w] are already final -> AND is exact greedy state
                bool hit = (mw & kw) != 0u;
                if (__any_sync(0xFFFFFFFFu, hit)) {
                    if (lane == w) kw &= ~(1u << (unsigned)b);
                }
            }
        }
        if (lane < nwm) skw[lane] = kw;
    }
    __syncthreads();

    // ---- output: each class block writes its own ranks ----
    for (unsigned p = t; p < m; p += 1024u) {
        unsigned i = sidx[p];
        bool kp = ((skw[p >> 5] >> (p & 31u)) & 1u) != 0u;
        out[i * 5 + 0] = kp ? g_obox[i * 4 + 0] : 0.f;
        out[i * 5 + 1] = kp ? g_obox[i * 4 + 1] : 0.f;
        out[i * 5 + 2] = kp ? g_obox[i * 4 + 2] : 0.f;
        out[i * 5 + 3] = kp ? g_obox[i * 4 + 3] : 0.f;
        out[i * 5 + 4] = kp ? g_oscore[i] : 0.f;
    }
    // safety: zero any slots beyond nvalid (normally none; n >= 2048)
    if (c == 0) {
        for (unsigned i = nvalid + t; i < TTOP; i += 1024u) {
            out[i * 5 + 0] = 0.f; out[i * 5 + 1] = 0.f; out[i * 5 + 2] = 0.f;
            out[i * 5 + 3] = 0.f; out[i * 5 + 4] = 0.f;
        }
    }
}

// ---------------- launch ----------------
extern "C" void kernel_launch(void* const* d_in, const int* in_sizes, int n_in,
                              void* d_out, int out_size) {
    const float* boxes  = nullptr;
    const float* scores = nullptr;
    const float* center = nullptr;
    for (int i = 0; i < n_in; i++) {
        if (in_sizes[i] == RBOX * 4)       boxes  = (const float*)d_in[i];
        else if (in_sizes[i] == RBOX * 11) scores = (const float*)d_in[i];
        else if (in_sizes[i] == RBOX)      center = (const float*)d_in[i];
    }
    if (!boxes)  boxes  = (const float*)d_in[0];
    if (!scores) scores = (const float*)d_in[1];
    if (!center) center = (const float*)d_in[2];
    float* out = (float*)d_out;

    k_rowmax<<<RMB, RMT>>>(scores, center);                    // + fused theta_r scan
    k_collect<<<(NGRP * 32 + 255) / 256, 256>>>(scores, center);
    k_rank<<<(CAP * 32 + 1023) / 1024, 1024>>>(boxes);
    k_nms<<<KCLS, 1024>>>(out);                                // per-class greedy + output
}